// round 15
// baseline (speedup 1.0000x reference)
#include <cuda_runtime.h>
#include <cstdint>
#include <math.h>

// ---- smem float offsets (feature+attn kernel) ----
#define OH2   0       // h halo 14*128 = 1792
#define OX2   1792    // x halo 14*16 = 224
#define OZT2  2016    // zt 14*64 = 896
#define OWHH2 2912    // wh 14*64 = 896
#define OC2   3808    // gemm partials 4*14*64 = 3584
#define OSI   7392    // si 8*32
#define OSJ   7648    // sj 14*32 = 448
#define OSDP  8096    // 4*32
#define OBM   8224    // 32
#define OWM2  8256    // 32
#define OU1   8288    // 14 (pad 16)
#define OU2   8304    // 14 (pad 16)
#define OES   8320    // 64
#define OAT   8384    // 64
#define OCS   8448    // cs 8*128 = 1024
#define OZR   9472    // z 8*64
#define ONRM  9984    // 32
#define ORED  10016   // 8
#define SMEMA 10048   // kernel A floats (~39KB)
// ---- logits kernel layout ----
#define CPART 16384   // colPart 8*128
#define SMEMB 17408   // kernel B floats (68KB)

// ---------------- scratch (device globals) ----------------
__device__ float4 g_qfrag[2048*32];   // [row][S][j]: {a0hi,a1hi,a0lo,a1lo}
__device__ float4 g_kfrag[2048*32];   // [col/8][S][col%8][j]: {b0hi,b1hi,b0lo,b1lo}
__device__ float g_rowsum[2048];
__device__ float g_colsum[2048];
__device__ float g_diag[2048];
__device__ float g_meanpart[256*64];
__device__ float g_timepart[256];
__device__ float g_znfirst[256*64];
__device__ float g_znlast[256*64];
__device__ unsigned int g_done = 0;

// Fast exp on FMA pipe (cephes exp2f poly); |x| <= ~80.
__device__ __forceinline__ float fexp(float x){
    float y = x * 1.44269504088896341f;
    float n = rintf(y);
    float f = y - n;
    float p = 1.535336188319500e-4f;
    p = fmaf(p, f, 1.339887440266574e-3f);
    p = fmaf(p, f, 9.618437357674640e-3f);
    p = fmaf(p, f, 5.550332471162809e-2f);
    p = fmaf(p, f, 2.402264791363012e-1f);
    p = fmaf(p, f, 6.931472028550421e-1f);
    p = fmaf(p, f, 1.0f);
    int e = (int)n;
    return p * __int_as_float((e + 127) << 23);
}

__device__ __forceinline__ float tf32hi(float x){
    uint32_t u;
    asm("cvt.rna.tf32.f32 %0, %1;" : "=r"(u) : "f"(x));
    return __uint_as_float(u);
}

__device__ __forceinline__ void mma8(float* d, float4 a, uint32_t b0, uint32_t b1){
    asm volatile(
        "mma.sync.aligned.m16n8k8.row.col.f32.tf32.tf32.f32 "
        "{%0,%1,%2,%3}, {%4,%5,%6,%7}, {%8,%9}, {%0,%1,%2,%3};\n"
        : "+f"(d[0]), "+f"(d[1]), "+f"(d[2]), "+f"(d[3])
        : "r"(__float_as_uint(a.x)), "r"(__float_as_uint(a.y)),
          "r"(__float_as_uint(a.z)), "r"(__float_as_uint(a.w)),
          "r"(b0), "r"(b1));
}

// ======================= KERNEL A: features + attention ====================
__global__ void __launch_bounds__(256, 3)
feat_kernel(const float* __restrict__ h,      const float* __restrict__ x_raw,
            const float* __restrict__ W_in,   const float* __restrict__ b_in,
            const float* __restrict__ dt_emb, const float* __restrict__ Wm1,
            const float* __restrict__ bm1,    const float* __restrict__ Wm2,
            const float* __restrict__ bm2,    const float* __restrict__ Wg,
            const float* __restrict__ a1,     const float* __restrict__ a2,
            const float* __restrict__ Wf,     const float* __restrict__ bf)
{
    extern __shared__ float sm[];

    const int tid  = threadIdx.x;
    const int gb   = blockIdx.x;       // 0..255
    const int lane = tid & 31;
    const int wid  = tid >> 5;
    const int c    = tid & 63;
    const int quad = tid >> 6;
    const int rp   = tid >> 6;

    const int gbase = gb*8;
    const int lo = gbase & ~511, hi = lo + 511;
    const int i0 = gbase & 511;

    if (tid < 8)       g_rowsum[gbase + tid] = 0.f;
    else if (tid < 16) g_colsum[gbase + tid - 8] = 0.f;

    // stage h (14 halo rows) and x (14), clamped at sequence edges
    for (int idx = tid; idx < 448; idx += 256){
        int hr = idx >> 5, p = idx & 31;
        int gr = gbase - 3 + hr; gr = gr < lo ? lo : (gr > hi ? hi : gr);
        ((float4*)(sm + OH2))[idx] = ((const float4*)h)[gr*32 + p];
    }
    if (tid < 56){
        int hr = tid >> 2, p = tid & 3;
        int gr = gbase - 3 + hr; gr = gr < lo ? lo : (gr > hi ? hi : gr);
        ((float4*)(sm + OX2))[tid] = ((const float4*)x_raw)[gr*4 + p];
    }
    if (tid >= 64 && tid < 192){
        int t = (tid - 64) >> 5, m = tid & 31;
        float s = 0.f;
        #pragma unroll
        for (int e = 0; e < 8; e++)
            s = fmaf(dt_emb[t*8 + e], Wm1[(32 + e)*32 + m], s);
        sm[OSDP + (tid - 64)] = s;
    } else if (tid >= 192 && tid < 224) sm[OBM  + tid - 192] = bm1[tid - 192];
    else if (tid >= 224)                sm[OWM2 + tid - 224] = Wm2[tid - 224];
    const float bm2v = bm2[0];
    __syncthreads();

    // GEMM1 partials: zt_pre = h @ W_in, 14 rows, quad-split K
    {
        float acc[14];
        #pragma unroll
        for (int r = 0; r < 14; r++) acc[r] = 0.f;
        const float4* H4 = (const float4*)(sm + OH2);
        #pragma unroll
        for (int kk = 0; kk < 8; kk++){
            int kb = quad*32 + kk*4;
            float w0 = W_in[(kb+0)*64 + c];
            float w1 = W_in[(kb+1)*64 + c];
            float w2 = W_in[(kb+2)*64 + c];
            float w3 = W_in[(kb+3)*64 + c];
            #pragma unroll
            for (int r = 0; r < 14; r++){
                float4 v = H4[r*32 + (kb>>2)];
                acc[r] = fmaf(w0, v.x, fmaf(w1, v.y, fmaf(w2, v.z, fmaf(w3, v.w, acc[r]))));
            }
        }
        #pragma unroll
        for (int r = 0; r < 14; r++) sm[OC2 + quad*896 + r*64 + c] = acc[r];
    }
    // si (center 8) / sj (14): warp t -> halo row t
    for (int t = wid; t < 14; t += 8){
        const float* xp = sm + OX2 + t*16;
        float si = 0.f, sj = 0.f;
        #pragma unroll
        for (int q = 0; q < 16; q++){
            float xv = xp[q];
            si = fmaf(xv, Wm1[q*32 + lane], si);
            sj = fmaf(xv, Wm1[(16+q)*32 + lane], sj);
        }
        sm[OSJ + t*32 + lane] = sj;
        if (t >= 3 && t < 11) sm[OSI + (t-3)*32 + lane] = si;
    }
    __syncthreads();

    // zt combine (14 rows)
    {
        float bi = b_in[c];
        for (int r = rp; r < 14; r += 4){
            float z = bi + sm[OC2 + 0*896 + r*64 + c] + sm[OC2 + 1*896 + r*64 + c]
                         + sm[OC2 + 2*896 + r*64 + c] + sm[OC2 + 3*896 + r*64 + c];
            sm[OZT2 + r*64 + c] = fmaxf(z, 0.f);
        }
    }
    __syncthreads();

    // GEMM2 partials: wh = zt @ Wg, 14 rows, K=64
    {
        float acc[14];
        #pragma unroll
        for (int r = 0; r < 14; r++) acc[r] = 0.f;
        const float4* Z4 = (const float4*)(sm + OZT2);
        #pragma unroll
        for (int kk = 0; kk < 4; kk++){
            int kb = quad*16 + kk*4;
            float w0 = Wg[(kb+0)*64 + c];
            float w1 = Wg[(kb+1)*64 + c];
            float w2 = Wg[(kb+2)*64 + c];
            float w3 = Wg[(kb+3)*64 + c];
            #pragma unroll
            for (int r = 0; r < 14; r++){
                float4 v = Z4[r*16 + (kb>>2)];
                acc[r] = fmaf(w0, v.x, fmaf(w1, v.y, fmaf(w2, v.z, fmaf(w3, v.w, acc[r]))));
            }
        }
        #pragma unroll
        for (int r = 0; r < 14; r++) sm[OC2 + quad*896 + r*64 + c] = acc[r];
    }
    __syncthreads();
    {
        for (int r = rp; r < 14; r += 4){
            float whv = sm[OC2 + 0*896 + r*64 + c] + sm[OC2 + 1*896 + r*64 + c]
                      + sm[OC2 + 2*896 + r*64 + c] + sm[OC2 + 3*896 + r*64 + c];
            sm[OWHH2 + r*64 + c] = whv;
        }
    }
    __syncthreads();

    // u1/u2 for 14 halo rows
    for (int t = wid; t < 14; t += 8){
        const float* whp = sm + OWHH2 + t*64;
        float v1 = whp[lane]*a1[lane] + whp[lane+32]*a1[lane+32];
        float v2 = whp[lane]*a2[lane] + whp[lane+32]*a2[lane+32];
        #pragma unroll
        for (int s = 16; s > 0; s >>= 1){
            v1 += __shfl_down_sync(0xffffffffu, v1, s);
            v2 += __shfl_down_sync(0xffffffffu, v2, s);
        }
        if (lane == 0){
            sm[OU1 + t] = v1;
            sm[OU2 + t] = v2;
        }
    }
    __syncthreads();

    // bias: 56 warp-tasks (center row r, offset o)
    for (int t = wid; t < 56; t += 8){
        int r = t / 7, o = t - r*7;
        int jl = i0 + r - 3 + o;
        int jj = r + o;                    // halo index of j
        int dtv = 3 - o; if (dtv < 0) dtv = 0;
        float v = sm[OSI + r*32 + lane] + sm[OSJ + jj*32 + lane]
                + sm[OSDP + dtv*32 + lane] + sm[OBM + lane];
        float p = v > 0.f ? v * sm[OWM2 + lane] : 0.f;
        #pragma unroll
        for (int s = 16; s > 0; s >>= 1) p += __shfl_down_sync(0xffffffffu, p, s);
        if (lane == 0){
            float e = -1e30f;
            if (jl >= 0 && jl < 512){
                float u = sm[OU1 + r + 3] + sm[OU2 + jj];
                float lr = u > 0.f ? u : 0.2f*u;
                e = lr + p + bm2v - 0.2f*(float)dtv;
            }
            sm[OES + r*8 + o] = e;
        }
    }
    __syncthreads();
    if (tid < 8){
        float mx = -1e30f;
        #pragma unroll
        for (int o = 0; o < 7; o++) mx = fmaxf(mx, sm[OES + tid*8 + o]);
        float sum = 0.f, ex[7];
        #pragma unroll
        for (int o = 0; o < 7; o++){
            float e = sm[OES + tid*8 + o];
            ex[o] = e > -1e29f ? fexp(e - mx) : 0.f;
            sum += ex[o];
        }
        float inv = 1.f / sum;
        #pragma unroll
        for (int o = 0; o < 7; o++) sm[OAT + tid*8 + o] = ex[o]*inv;
    }
    __syncthreads();

    // zg = elu(attn @ wh); cs = [zt | zg]  (center rows)
    {
        #pragma unroll
        for (int s = 0; s < 2; s++){
            int rr = rp + s*4;
            float acc = 0.f;
            #pragma unroll
            for (int o = 0; o < 7; o++)
                acc = fmaf(sm[OAT + rr*8 + o], sm[OWHH2 + (rr+o)*64 + c], acc);
            float zg = acc > 0.f ? acc : fexp(acc) - 1.f;
            sm[OCS + rr*128 + 64 + c] = zg;
            sm[OCS + rr*128 + c]      = sm[OZT2 + (rr+3)*64 + c];
        }
    }
    __syncthreads();

    // GEMM3 partials: z = cs @ Wf, 8 center rows, K=128
    {
        float acc[8] = {0,0,0,0,0,0,0,0};
        const float4* C4 = (const float4*)(sm + OCS);
        #pragma unroll
        for (int kk = 0; kk < 8; kk++){
            int kb = quad*32 + kk*4;
            float w0 = Wf[(kb+0)*64 + c];
            float w1 = Wf[(kb+1)*64 + c];
            float w2 = Wf[(kb+2)*64 + c];
            float w3 = Wf[(kb+3)*64 + c];
            #pragma unroll
            for (int r = 0; r < 8; r++){
                float4 v = C4[r*32 + (kb>>2)];
                acc[r] = fmaf(w0, v.x, fmaf(w1, v.y, fmaf(w2, v.z, fmaf(w3, v.w, acc[r]))));
            }
        }
        #pragma unroll
        for (int r = 0; r < 8; r++) sm[OC2 + quad*512 + r*64 + c] = acc[r];
    }
    __syncthreads();
    {
        float bfc = bf[c];
        #pragma unroll
        for (int s = 0; s < 2; s++){
            int rr = rp + s*4;
            float z = bfc + sm[OC2 + 0*512 + rr*64 + c] + sm[OC2 + 1*512 + rr*64 + c]
                          + sm[OC2 + 2*512 + rr*64 + c] + sm[OC2 + 3*512 + rr*64 + c];
            sm[OZR + rr*64 + c] = fmaxf(z, 0.f);
        }
    }
    __syncthreads();

    // norms: 32 warp-tasks (8 rows x {z, zt, zg, zt.zg})
    for (int t = wid; t < 32; t += 8){
        int r = t >> 2, which = t & 3;
        float v;
        if (which == 0){
            float x1 = sm[OZR + r*64 + lane], x2 = sm[OZR + r*64 + lane + 32];
            v = x1*x1 + x2*x2;
        } else if (which == 1){
            float x1 = sm[OZT2 + (r+3)*64 + lane], x2 = sm[OZT2 + (r+3)*64 + lane + 32];
            v = x1*x1 + x2*x2;
        } else if (which == 2){
            float x1 = sm[OCS + r*128 + 64 + lane], x2 = sm[OCS + r*128 + 96 + lane];
            v = x1*x1 + x2*x2;
        } else {
            v = sm[OZT2 + (r+3)*64 + lane]      * sm[OCS + r*128 + 64 + lane]
              + sm[OZT2 + (r+3)*64 + lane + 32] * sm[OCS + r*128 + 96 + lane];
        }
        #pragma unroll
        for (int s = 16; s > 0; s >>= 1) v += __shfl_down_sync(0xffffffffu, v, s);
        if (lane == 0) sm[ONRM + r*4 + which] = v;
    }
    __syncthreads();

    // diag
    if (tid < 8){
        float invzt = 1.f / fmaxf(sqrtf(sm[ONRM + tid*4 + 1]), 1e-8f);
        float invzg = 1.f / fmaxf(sqrtf(sm[ONRM + tid*4 + 2]), 1e-8f);
        g_diag[gbase + tid] = 10.f * sm[ONRM + tid*4 + 3] * invzt * invzg;
    }
    // q fragments: row-major [row][S][j]
    {
        int row = tid >> 5;           // 0..7
        int S   = (tid >> 2) & 7;
        int j   = tid & 3;
        float invzt = 1.f / fmaxf(sqrtf(sm[ONRM + row*4 + 1]), 1e-8f);
        float q0 = sm[OZT2 + (row+3)*64 + S*8 + j]     * invzt;
        float q1 = sm[OZT2 + (row+3)*64 + S*8 + 4 + j] * invzt;
        float q0h = tf32hi(q0), q1h = tf32hi(q1);
        g_qfrag[(gbase + row)*32 + S*4 + j] =
            make_float4(q0h, q1h, tf32hi(q0 - q0h), tf32hi(q1 - q1h));
    }
    // k fragments: GROUP-major [group=gb][S][colq=row][j] -> linear stage in logits
    {
        int row = tid >> 5;           // 0..7 = colq
        int S   = (tid >> 2) & 7;
        int j   = tid & 3;
        float invzg = 1.f / fmaxf(sqrtf(sm[ONRM + row*4 + 2]), 1e-8f);
        float b0 = sm[OCS + row*128 + 64 + S*8 + j]     * invzg;
        float b1 = sm[OCS + row*128 + 64 + S*8 + 4 + j] * invzg;
        float b0h = tf32hi(b0), b1h = tf32hi(b1);
        g_kfrag[gb*256 + S*32 + row*4 + j] =
            make_float4(b0h, b1h, tf32hi(b0 - b0h), tf32hi(b1 - b1h));
    }
    if (tid < 64){
        float ms = 0.f;
        float zn0 = 0.f, zn7 = 0.f;
        #pragma unroll
        for (int r = 0; r < 8; r++){
            float invz = 1.f / fmaxf(sqrtf(sm[ONRM + r*4]), 1e-8f);
            float zn = sm[OZR + r*64 + tid] * invz;
            ms += zn;
            if (r == 0) zn0 = zn;
            if (r == 7) zn7 = zn;
        }
        g_meanpart[gb*64 + tid] = ms;
        g_znfirst[gb*64 + tid]  = zn0;
        g_znlast[gb*64 + tid]   = zn7;
    }
    if (wid < 7){
        int r = wid;
        float iz1 = 1.f / fmaxf(sqrtf(sm[ONRM + r*4]), 1e-8f);
        float iz2 = 1.f / fmaxf(sqrtf(sm[ONRM + (r+1)*4]), 1e-8f);
        float d = sm[OZR + r*64 + lane]      * sm[OZR + (r+1)*64 + lane]
                + sm[OZR + r*64 + lane + 32] * sm[OZR + (r+1)*64 + lane + 32];
        #pragma unroll
        for (int s = 16; s > 0; s >>= 1) d += __shfl_down_sync(0xffffffffu, d, s);
        if (lane == 0){
            float dd = 1.f - d*iz1*iz2;
            sm[ORED + r] = dd*dd;
        }
    }
    __syncthreads();
    if (tid == 0){
        float ts = 0.f;
        #pragma unroll
        for (int r = 0; r < 7; r++) ts += sm[ORED + r];
        g_timepart[gb] = ts;
    }
}

// ================ KERNEL B: cross pairs + tensor logits + final ============
__global__ void __launch_bounds__(256, 2)
logits_kernel(float* __restrict__ out)
{
    extern __shared__ float sm[];
    __shared__ unsigned int lastFlag;

    const int tid  = threadIdx.x;
    const int bid  = blockIdx.x;
    const int G    = gridDim.x;
    const int lane = tid & 31;
    const int wid  = tid >> 5;
    const int c    = tid & 63;
    const int quad = tid >> 6;

    // cross time-pair for group bid
    {
        int gb = bid;
        if ((gb & 63) != 63 && wid == 0){
            float d = g_znlast[gb*64 + lane]      * g_znfirst[(gb+1)*64 + lane]
                    + g_znlast[gb*64 + lane + 32] * g_znfirst[(gb+1)*64 + lane + 32];
            #pragma unroll
            for (int s = 16; s > 0; s >>= 1) d += __shfl_down_sync(0xffffffffu, d, s);
            if (lane == 0){
                float dd = 1.f - d;
                g_timepart[gb] += dd*dd;
            }
        }
    }

    // logits tile: 128x128; warp = 16 rows x 128 cols
    {
        const int rb = (bid & 15) << 7, cb = (bid >> 4) << 7;

        // stage B fragments: LINEAR copy (group-major layout)
        {
            float4* BV = (float4*)sm;
            const float4* src = &g_kfrag[cb*32];   // (cb/8)*256
            #pragma unroll
            for (int it = 0; it < 16; it++)
                BV[it*256 + tid] = src[it*256 + tid];
        }
        __syncthreads();

        float acc[16][4];
        #pragma unroll
        for (int n = 0; n < 16; n++){
            acc[n][0] = 0.f; acc[n][1] = 0.f; acc[n][2] = 0.f; acc[n][3] = 0.f;
        }

        // A fragments: 2 x LDG.128 per S (rows r and r+8)
        const float4* qf = &g_qfrag[(rb + wid*16 + (lane >> 2))*32 + (lane & 3)];
        const float4* BV = (const float4*)sm;

        #pragma unroll
        for (int S = 0; S < 8; S++){
            float4 f0 = qf[S*4];            // row r
            float4 f1 = qf[8*32 + S*4];     // row r+8
            float4 ah = make_float4(f0.x, f1.x, f0.y, f1.y);
            float4 al = make_float4(f0.z, f1.z, f0.w, f1.w);
            // smem element for (n, S, colq, j): group n at n*256, then S*32 + colq*4 + j
            #pragma unroll
            for (int n = 0; n < 16; n++){
                float4 bb = BV[n*256 + S*32 + lane];
                uint32_t b0h = __float_as_uint(bb.x), b1h = __float_as_uint(bb.y);
                uint32_t b0l = __float_as_uint(bb.z), b1l = __float_as_uint(bb.w);
                mma8(acc[n], ah, b0h, b1h);
                mma8(acc[n], ah, b0l, b1l);
                mma8(acc[n], al, b0h, b1h);
            }
        }

        // epilogue: exp + row/col sums
        float* colPart = sm + CPART;
        float rlo = 0.f, rhi = 0.f;
        #pragma unroll
        for (int n = 0; n < 16; n++){
            float e0 = fexp(acc[n][0] * 10.f);
            float e1 = fexp(acc[n][1] * 10.f);
            float e2 = fexp(acc[n][2] * 10.f);
            float e3 = fexp(acc[n][3] * 10.f);
            rlo += e0 + e1; rhi += e2 + e3;
            float ca = e0 + e2, cbv = e1 + e3;
            #pragma unroll
            for (int o = 4; o < 32; o <<= 1){
                ca  += __shfl_xor_sync(0xffffffffu, ca,  o);
                cbv += __shfl_xor_sync(0xffffffffu, cbv, o);
            }
            if (lane < 4){
                colPart[wid*128 + n*8 + 2*lane]     = ca;
                colPart[wid*128 + n*8 + 2*lane + 1] = cbv;
            }
        }
        rlo += __shfl_xor_sync(0xffffffffu, rlo, 1);
        rlo += __shfl_xor_sync(0xffffffffu, rlo, 2);
        rhi += __shfl_xor_sync(0xffffffffu, rhi, 1);
        rhi += __shfl_xor_sync(0xffffffffu, rhi, 2);
        if ((lane & 3) == 0){
            atomicAdd(&g_rowsum[rb + wid*16 + (lane >> 2)],     rlo);
            atomicAdd(&g_rowsum[rb + wid*16 + 8 + (lane >> 2)], rhi);
        }
        __syncthreads();
        if (tid < 128){
            float s2 = 0.f;
            #pragma unroll
            for (int w2 = 0; w2 < 8; w2++) s2 += colPart[w2*128 + tid];
            atomicAdd(&g_colsum[cb + tid], s2);
        }
    }

    // ---- final combine: last block ----
    __threadfence();
    __syncthreads();
    if (tid == 0){
        unsigned t = atomicAdd(&g_done, 1u);
        lastFlag = (t == (unsigned)G - 1u) ? 1u : 0u;
    }
    __syncthreads();
    if (lastFlag){
        float ms = 0.f;
        for (int blk = quad; blk < 256; blk += 4)
            ms += __ldcg(&g_meanpart[blk*64 + c]);
        __syncthreads();
        sm[tid] = ms;
        __syncthreads();
        if (tid < 64){
            float Mv = sm[tid] + sm[64+tid] + sm[128+tid] + sm[192+tid];
            sm[256 + tid] = Mv*Mv;
        }
        __syncthreads();

        float tv = __ldcg(&g_timepart[tid]);
        float s = 0.f;
        for (int r = tid; r < 2048; r += 256)
            s += __logf(__ldcg(&g_rowsum[r])) + __logf(__ldcg(&g_colsum[r]))
               - 2.f*__ldcg(&g_diag[r]);
        sm[512 + tid] = tv;
        sm[768 + tid] = s;
        __syncthreads();
        for (int st = 128; st > 0; st >>= 1){
            if (tid < st){
                sm[512+tid] += sm[512+tid+st];
                sm[768+tid] += sm[768+tid+st];
            }
            __syncthreads();
        }
        if (tid == 0){
            float nm2 = 0.f;
            #pragma unroll
            for (int i = 0; i < 64; i++) nm2 += sm[256 + i];
            float normM = sqrtf(nm2);
            float l_con = 0.5f * sm[768] / 2048.f;
            float l_sc  = -normM / 2048.f;
            float l_t   =  sm[512] / 2044.f;
            out[0] = l_con + l_sc + l_t;
            out[1] = l_con;
            out[2] = l_sc;
            out[3] = l_t;
            g_done = 0;   // reset for next graph replay
        }
    }
}

// ---------------- launch ----------------
extern "C" void kernel_launch(void* const* d_in, const int* in_sizes, int n_in,
                              void* d_out, int out_size){
    const float* h      = (const float*)d_in[0];
    const float* x_raw  = (const float*)d_in[1];
    const float* W_in   = (const float*)d_in[2];
    const float* b_in   = (const float*)d_in[3];
    const float* dt_emb = (const float*)d_in[4];
    const float* Wm1    = (const float*)d_in[5];
    const float* bm1    = (const float*)d_in[6];
    const float* Wm2    = (const float*)d_in[7];
    const float* bm2    = (const float*)d_in[8];
    const float* Wg     = (const float*)d_in[9];
    const float* a1     = (const float*)d_in[10];
    const float* a2     = (const float*)d_in[11];
    const float* Wf     = (const float*)d_in[12];
    const float* bf     = (const float*)d_in[13];
    float* out = (float*)d_out;

    const int SMA = SMEMA * 4;
    const int SMB = SMEMB * 4;
    cudaFuncSetAttribute(feat_kernel,   cudaFuncAttributeMaxDynamicSharedMemorySize, SMA);
    cudaFuncSetAttribute(logits_kernel, cudaFuncAttributeMaxDynamicSharedMemorySize, SMB);

    feat_kernel<<<256, 256, SMA>>>(h, x_raw, W_in, b_in, dt_emb, Wm1, bm1, Wm2,
                                   bm2, Wg, a1, a2, Wf, bf);
    logits_kernel<<<256, 256, SMB>>>(out);
}

// round 16
// speedup vs baseline: 1.0472x; 1.0472x over previous
#include <cuda_runtime.h>
#include <cstdint>
#include <math.h>

// ---- smem float offsets (feature+attn kernel) ----
#define OH2   0       // h halo 14*128 = 1792
#define OX2   1792    // x halo 14*16 = 224
#define OZT2  2016    // zt 14*64 = 896
#define OWHH2 2912    // wh 14*64 = 896
#define OC2   3808    // gemm partials 4*14*64 = 3584
#define OSI   7392    // si 8*32
#define OSJ   7648    // sj 14*32 = 448
#define OSDP  8096    // 4*32
#define OBM   8224    // 32
#define OWM2  8256    // 32
#define OU1   8288    // 14 (pad 16)
#define OU2   8304    // 14 (pad 16)
#define OES   8320    // 64
#define OAT   8384    // 64
#define OCS   8448    // cs 8*128 = 1024
#define OZR   9472    // z 8*64
#define ONRM  9984    // 32
#define ORED  10016   // 8
#define SMEMA 10048   // kernel A floats (~39KB)
// ---- logits kernel layout ----
#define SMEMB 1056    // colPart 8*128 + final-combine scratch (4.2KB)

// ---------------- scratch (device globals) ----------------
__device__ float4 g_qfrag[2048*32];   // [row][S][j]: {a0hi,a1hi,a0lo,a1lo}
__device__ float4 g_kfrag[2048*32];   // [col/8][S][col%8][j]: {b0hi,b1hi,b0lo,b1lo}, pre-scaled x10
__device__ float g_rowsum[2048];
__device__ float g_colsum[2048];
__device__ float g_diag[2048];
__device__ float g_meanpart[256*64];
__device__ float g_timepart[256];
__device__ float g_znfirst[256*64];
__device__ float g_znlast[256*64];
__device__ unsigned int g_done = 0;

// Fast exp on FMA pipe (cephes exp2f poly); |x| <= ~80.
__device__ __forceinline__ float fexp(float x){
    float y = x * 1.44269504088896341f;
    float n = rintf(y);
    float f = y - n;
    float p = 1.535336188319500e-4f;
    p = fmaf(p, f, 1.339887440266574e-3f);
    p = fmaf(p, f, 9.618437357674640e-3f);
    p = fmaf(p, f, 5.550332471162809e-2f);
    p = fmaf(p, f, 2.402264791363012e-1f);
    p = fmaf(p, f, 6.931472028550421e-1f);
    p = fmaf(p, f, 1.0f);
    int e = (int)n;
    return p * __int_as_float((e + 127) << 23);
}

// Degree-4 exp (rel err ~1e-5): plenty for the 1e-3 tolerance, saves 2 FFMA.
__device__ __forceinline__ float fexp4(float x){
    float y = x * 1.44269504088896341f;
    float n = rintf(y);
    float f = y - n;
    float p = 9.618129107628477e-3f;
    p = fmaf(p, f, 5.550410866482158e-2f);
    p = fmaf(p, f, 2.402265069591012e-1f);
    p = fmaf(p, f, 6.931471805599453e-1f);
    p = fmaf(p, f, 1.0f);
    int e = (int)n;
    return p * __int_as_float((e + 127) << 23);
}

__device__ __forceinline__ float tf32hi(float x){
    uint32_t u;
    asm("cvt.rna.tf32.f32 %0, %1;" : "=r"(u) : "f"(x));
    return __uint_as_float(u);
}

__device__ __forceinline__ void mma8(float* d, float4 a, uint32_t b0, uint32_t b1){
    asm volatile(
        "mma.sync.aligned.m16n8k8.row.col.f32.tf32.tf32.f32 "
        "{%0,%1,%2,%3}, {%4,%5,%6,%7}, {%8,%9}, {%0,%1,%2,%3};\n"
        : "+f"(d[0]), "+f"(d[1]), "+f"(d[2]), "+f"(d[3])
        : "r"(__float_as_uint(a.x)), "r"(__float_as_uint(a.y)),
          "r"(__float_as_uint(a.z)), "r"(__float_as_uint(a.w)),
          "r"(b0), "r"(b1));
}

// ======================= KERNEL A: features + attention ====================
__global__ void __launch_bounds__(256, 3)
feat_kernel(const float* __restrict__ h,      const float* __restrict__ x_raw,
            const float* __restrict__ W_in,   const float* __restrict__ b_in,
            const float* __restrict__ dt_emb, const float* __restrict__ Wm1,
            const float* __restrict__ bm1,    const float* __restrict__ Wm2,
            const float* __restrict__ bm2,    const float* __restrict__ Wg,
            const float* __restrict__ a1,     const float* __restrict__ a2,
            const float* __restrict__ Wf,     const float* __restrict__ bf)
{
    extern __shared__ float sm[];

    const int tid  = threadIdx.x;
    const int gb   = blockIdx.x;       // 0..255
    const int lane = tid & 31;
    const int wid  = tid >> 5;
    const int c    = tid & 63;
    const int quad = tid >> 6;
    const int rp   = tid >> 6;

    const int gbase = gb*8;
    const int lo = gbase & ~511, hi = lo + 511;
    const int i0 = gbase & 511;

    if (tid < 8)       g_rowsum[gbase + tid] = 0.f;
    else if (tid < 16) g_colsum[gbase + tid - 8] = 0.f;

    // stage h (14 halo rows) and x (14), clamped at sequence edges
    for (int idx = tid; idx < 448; idx += 256){
        int hr = idx >> 5, p = idx & 31;
        int gr = gbase - 3 + hr; gr = gr < lo ? lo : (gr > hi ? hi : gr);
        ((float4*)(sm + OH2))[idx] = ((const float4*)h)[gr*32 + p];
    }
    if (tid < 56){
        int hr = tid >> 2, p = tid & 3;
        int gr = gbase - 3 + hr; gr = gr < lo ? lo : (gr > hi ? hi : gr);
        ((float4*)(sm + OX2))[tid] = ((const float4*)x_raw)[gr*4 + p];
    }
    if (tid >= 64 && tid < 192){
        int t = (tid - 64) >> 5, m = tid & 31;
        float s = 0.f;
        #pragma unroll
        for (int e = 0; e < 8; e++)
            s = fmaf(dt_emb[t*8 + e], Wm1[(32 + e)*32 + m], s);
        sm[OSDP + (tid - 64)] = s;
    } else if (tid >= 192 && tid < 224) sm[OBM  + tid - 192] = bm1[tid - 192];
    else if (tid >= 224)                sm[OWM2 + tid - 224] = Wm2[tid - 224];
    const float bm2v = bm2[0];
    __syncthreads();

    // GEMM1 partials: zt_pre = h @ W_in, 14 rows, quad-split K
    {
        float acc[14];
        #pragma unroll
        for (int r = 0; r < 14; r++) acc[r] = 0.f;
        const float4* H4 = (const float4*)(sm + OH2);
        #pragma unroll
        for (int kk = 0; kk < 8; kk++){
            int kb = quad*32 + kk*4;
            float w0 = W_in[(kb+0)*64 + c];
            float w1 = W_in[(kb+1)*64 + c];
            float w2 = W_in[(kb+2)*64 + c];
            float w3 = W_in[(kb+3)*64 + c];
            #pragma unroll
            for (int r = 0; r < 14; r++){
                float4 v = H4[r*32 + (kb>>2)];
                acc[r] = fmaf(w0, v.x, fmaf(w1, v.y, fmaf(w2, v.z, fmaf(w3, v.w, acc[r]))));
            }
        }
        #pragma unroll
        for (int r = 0; r < 14; r++) sm[OC2 + quad*896 + r*64 + c] = acc[r];
    }
    // si (center 8) / sj (14): warp t -> halo row t
    for (int t = wid; t < 14; t += 8){
        const float* xp = sm + OX2 + t*16;
        float si = 0.f, sj = 0.f;
        #pragma unroll
        for (int q = 0; q < 16; q++){
            float xv = xp[q];
            si = fmaf(xv, Wm1[q*32 + lane], si);
            sj = fmaf(xv, Wm1[(16+q)*32 + lane], sj);
        }
        sm[OSJ + t*32 + lane] = sj;
        if (t >= 3 && t < 11) sm[OSI + (t-3)*32 + lane] = si;
    }
    __syncthreads();

    // zt combine (14 rows)
    {
        float bi = b_in[c];
        for (int r = rp; r < 14; r += 4){
            float z = bi + sm[OC2 + 0*896 + r*64 + c] + sm[OC2 + 1*896 + r*64 + c]
                         + sm[OC2 + 2*896 + r*64 + c] + sm[OC2 + 3*896 + r*64 + c];
            sm[OZT2 + r*64 + c] = fmaxf(z, 0.f);
        }
    }
    __syncthreads();

    // GEMM2 partials: wh = zt @ Wg, 14 rows, K=64
    {
        float acc[14];
        #pragma unroll
        for (int r = 0; r < 14; r++) acc[r] = 0.f;
        const float4* Z4 = (const float4*)(sm + OZT2);
        #pragma unroll
        for (int kk = 0; kk < 4; kk++){
            int kb = quad*16 + kk*4;
            float w0 = Wg[(kb+0)*64 + c];
            float w1 = Wg[(kb+1)*64 + c];
            float w2 = Wg[(kb+2)*64 + c];
            float w3 = Wg[(kb+3)*64 + c];
            #pragma unroll
            for (int r = 0; r < 14; r++){
                float4 v = Z4[r*16 + (kb>>2)];
                acc[r] = fmaf(w0, v.x, fmaf(w1, v.y, fmaf(w2, v.z, fmaf(w3, v.w, acc[r]))));
            }
        }
        #pragma unroll
        for (int r = 0; r < 14; r++) sm[OC2 + quad*896 + r*64 + c] = acc[r];
    }
    __syncthreads();
    {
        for (int r = rp; r < 14; r += 4){
            float whv = sm[OC2 + 0*896 + r*64 + c] + sm[OC2 + 1*896 + r*64 + c]
                      + sm[OC2 + 2*896 + r*64 + c] + sm[OC2 + 3*896 + r*64 + c];
            sm[OWHH2 + r*64 + c] = whv;
        }
    }
    __syncthreads();

    // u1/u2 for 14 halo rows
    for (int t = wid; t < 14; t += 8){
        const float* whp = sm + OWHH2 + t*64;
        float v1 = whp[lane]*a1[lane] + whp[lane+32]*a1[lane+32];
        float v2 = whp[lane]*a2[lane] + whp[lane+32]*a2[lane+32];
        #pragma unroll
        for (int s = 16; s > 0; s >>= 1){
            v1 += __shfl_down_sync(0xffffffffu, v1, s);
            v2 += __shfl_down_sync(0xffffffffu, v2, s);
        }
        if (lane == 0){
            sm[OU1 + t] = v1;
            sm[OU2 + t] = v2;
        }
    }
    __syncthreads();

    // bias: 56 warp-tasks (center row r, offset o)
    for (int t = wid; t < 56; t += 8){
        int r = t / 7, o = t - r*7;
        int jl = i0 + r - 3 + o;
        int jj = r + o;                    // halo index of j
        int dtv = 3 - o; if (dtv < 0) dtv = 0;
        float v = sm[OSI + r*32 + lane] + sm[OSJ + jj*32 + lane]
                + sm[OSDP + dtv*32 + lane] + sm[OBM + lane];
        float p = v > 0.f ? v * sm[OWM2 + lane] : 0.f;
        #pragma unroll
        for (int s = 16; s > 0; s >>= 1) p += __shfl_down_sync(0xffffffffu, p, s);
        if (lane == 0){
            float e = -1e30f;
            if (jl >= 0 && jl < 512){
                float u = sm[OU1 + r + 3] + sm[OU2 + jj];
                float lr = u > 0.f ? u : 0.2f*u;
                e = lr + p + bm2v - 0.2f*(float)dtv;
            }
            sm[OES + r*8 + o] = e;
        }
    }
    __syncthreads();
    if (tid < 8){
        float mx = -1e30f;
        #pragma unroll
        for (int o = 0; o < 7; o++) mx = fmaxf(mx, sm[OES + tid*8 + o]);
        float sum = 0.f, ex[7];
        #pragma unroll
        for (int o = 0; o < 7; o++){
            float e = sm[OES + tid*8 + o];
            ex[o] = e > -1e29f ? fexp(e - mx) : 0.f;
            sum += ex[o];
        }
        float inv = 1.f / sum;
        #pragma unroll
        for (int o = 0; o < 7; o++) sm[OAT + tid*8 + o] = ex[o]*inv;
    }
    __syncthreads();

    // zg = elu(attn @ wh); cs = [zt | zg]  (center rows)
    {
        #pragma unroll
        for (int s = 0; s < 2; s++){
            int rr = rp + s*4;
            float acc = 0.f;
            #pragma unroll
            for (int o = 0; o < 7; o++)
                acc = fmaf(sm[OAT + rr*8 + o], sm[OWHH2 + (rr+o)*64 + c], acc);
            float zg = acc > 0.f ? acc : fexp(acc) - 1.f;
            sm[OCS + rr*128 + 64 + c] = zg;
            sm[OCS + rr*128 + c]      = sm[OZT2 + (rr+3)*64 + c];
        }
    }
    __syncthreads();

    // GEMM3 partials: z = cs @ Wf, 8 center rows, K=128
    {
        float acc[8] = {0,0,0,0,0,0,0,0};
        const float4* C4 = (const float4*)(sm + OCS);
        #pragma unroll
        for (int kk = 0; kk < 8; kk++){
            int kb = quad*32 + kk*4;
            float w0 = Wf[(kb+0)*64 + c];
            float w1 = Wf[(kb+1)*64 + c];
            float w2 = Wf[(kb+2)*64 + c];
            float w3 = Wf[(kb+3)*64 + c];
            #pragma unroll
            for (int r = 0; r < 8; r++){
                float4 v = C4[r*32 + (kb>>2)];
                acc[r] = fmaf(w0, v.x, fmaf(w1, v.y, fmaf(w2, v.z, fmaf(w3, v.w, acc[r]))));
            }
        }
        #pragma unroll
        for (int r = 0; r < 8; r++) sm[OC2 + quad*512 + r*64 + c] = acc[r];
    }
    __syncthreads();
    {
        float bfc = bf[c];
        #pragma unroll
        for (int s = 0; s < 2; s++){
            int rr = rp + s*4;
            float z = bfc + sm[OC2 + 0*512 + rr*64 + c] + sm[OC2 + 1*512 + rr*64 + c]
                          + sm[OC2 + 2*512 + rr*64 + c] + sm[OC2 + 3*512 + rr*64 + c];
            sm[OZR + rr*64 + c] = fmaxf(z, 0.f);
        }
    }
    __syncthreads();

    // norms: 32 warp-tasks (8 rows x {z, zt, zg, zt.zg})
    for (int t = wid; t < 32; t += 8){
        int r = t >> 2, which = t & 3;
        float v;
        if (which == 0){
            float x1 = sm[OZR + r*64 + lane], x2 = sm[OZR + r*64 + lane + 32];
            v = x1*x1 + x2*x2;
        } else if (which == 1){
            float x1 = sm[OZT2 + (r+3)*64 + lane], x2 = sm[OZT2 + (r+3)*64 + lane + 32];
            v = x1*x1 + x2*x2;
        } else if (which == 2){
            float x1 = sm[OCS + r*128 + 64 + lane], x2 = sm[OCS + r*128 + 96 + lane];
            v = x1*x1 + x2*x2;
        } else {
            v = sm[OZT2 + (r+3)*64 + lane]      * sm[OCS + r*128 + 64 + lane]
              + sm[OZT2 + (r+3)*64 + lane + 32] * sm[OCS + r*128 + 96 + lane];
        }
        #pragma unroll
        for (int s = 16; s > 0; s >>= 1) v += __shfl_down_sync(0xffffffffu, v, s);
        if (lane == 0) sm[ONRM + r*4 + which] = v;
    }
    __syncthreads();

    // diag
    if (tid < 8){
        float invzt = 1.f / fmaxf(sqrtf(sm[ONRM + tid*4 + 1]), 1e-8f);
        float invzg = 1.f / fmaxf(sqrtf(sm[ONRM + tid*4 + 2]), 1e-8f);
        g_diag[gbase + tid] = 10.f * sm[ONRM + tid*4 + 3] * invzt * invzg;
    }
    // q fragments: row-major [row][S][j]
    {
        int row = tid >> 5;           // 0..7
        int S   = (tid >> 2) & 7;
        int j   = tid & 3;
        float invzt = 1.f / fmaxf(sqrtf(sm[ONRM + row*4 + 1]), 1e-8f);
        float q0 = sm[OZT2 + (row+3)*64 + S*8 + j]     * invzt;
        float q1 = sm[OZT2 + (row+3)*64 + S*8 + 4 + j] * invzt;
        float q0h = tf32hi(q0), q1h = tf32hi(q1);
        g_qfrag[(gbase + row)*32 + S*4 + j] =
            make_float4(q0h, q1h, tf32hi(q0 - q0h), tf32hi(q1 - q1h));
    }
    // k fragments: GROUP-major [group=gb][S][colq=row][j], PRE-SCALED by 10 (1/TEMP)
    {
        int row = tid >> 5;           // 0..7 = colq
        int S   = (tid >> 2) & 7;
        int j   = tid & 3;
        float scl = 10.f / fmaxf(sqrtf(sm[ONRM + row*4 + 2]), 1e-8f);
        float b0 = sm[OCS + row*128 + 64 + S*8 + j]     * scl;
        float b1 = sm[OCS + row*128 + 64 + S*8 + 4 + j] * scl;
        float b0h = tf32hi(b0), b1h = tf32hi(b1);
        g_kfrag[gb*256 + S*32 + row*4 + j] =
            make_float4(b0h, b1h, tf32hi(b0 - b0h), tf32hi(b1 - b1h));
    }
    if (tid < 64){
        float ms = 0.f;
        float zn0 = 0.f, zn7 = 0.f;
        #pragma unroll
        for (int r = 0; r < 8; r++){
            float invz = 1.f / fmaxf(sqrtf(sm[ONRM + r*4]), 1e-8f);
            float zn = sm[OZR + r*64 + tid] * invz;
            ms += zn;
            if (r == 0) zn0 = zn;
            if (r == 7) zn7 = zn;
        }
        g_meanpart[gb*64 + tid] = ms;
        g_znfirst[gb*64 + tid]  = zn0;
        g_znlast[gb*64 + tid]   = zn7;
    }
    if (wid < 7){
        int r = wid;
        float iz1 = 1.f / fmaxf(sqrtf(sm[ONRM + r*4]), 1e-8f);
        float iz2 = 1.f / fmaxf(sqrtf(sm[ONRM + (r+1)*4]), 1e-8f);
        float d = sm[OZR + r*64 + lane]      * sm[OZR + (r+1)*64 + lane]
                + sm[OZR + r*64 + lane + 32] * sm[OZR + (r+1)*64 + lane + 32];
        #pragma unroll
        for (int s = 16; s > 0; s >>= 1) d += __shfl_down_sync(0xffffffffu, d, s);
        if (lane == 0){
            float dd = 1.f - d*iz1*iz2;
            sm[ORED + r] = dd*dd;
        }
    }
    __syncthreads();
    if (tid == 0){
        float ts = 0.f;
        #pragma unroll
        for (int r = 0; r < 7; r++) ts += sm[ORED + r];
        g_timepart[gb] = ts;
    }
}

// ================ KERNEL B: cross pairs + tensor logits + final ============
__global__ void __launch_bounds__(256, 2)
logits_kernel(float* __restrict__ out)
{
    extern __shared__ float sm[];
    __shared__ unsigned int lastFlag;

    const int tid  = threadIdx.x;
    const int bid  = blockIdx.x;
    const int G    = gridDim.x;
    const int lane = tid & 31;
    const int wid  = tid >> 5;
    const int c    = tid & 63;
    const int quad = tid >> 6;

    // cross time-pair for group bid
    {
        int gb = bid;
        if ((gb & 63) != 63 && wid == 0){
            float d = g_znlast[gb*64 + lane]      * g_znfirst[(gb+1)*64 + lane]
                    + g_znlast[gb*64 + lane + 32] * g_znfirst[(gb+1)*64 + lane + 32];
            #pragma unroll
            for (int s = 16; s > 0; s >>= 1) d += __shfl_down_sync(0xffffffffu, d, s);
            if (lane == 0){
                float dd = 1.f - d;
                g_timepart[gb] += dd*dd;
            }
        }
    }

    // logits tile: 128x128; warp = 16 rows x 128 cols; B direct from global (L1-hot)
    {
        const int rb = (bid & 15) << 7, cb = (bid >> 4) << 7;

        float acc[16][4];
        #pragma unroll
        for (int n = 0; n < 16; n++){
            acc[n][0] = 0.f; acc[n][1] = 0.f; acc[n][2] = 0.f; acc[n][3] = 0.f;
        }

        const float4* qf = &g_qfrag[(rb + wid*16 + (lane >> 2))*32 + (lane & 3)];
        const float4* BV = &g_kfrag[cb*32];   // group-major: n*256 + S*32 + (colq*4+j)

        #pragma unroll
        for (int S = 0; S < 8; S++){
            float4 f0 = qf[S*4];            // row r
            float4 f1 = qf[8*32 + S*4];     // row r+8
            float4 ah = make_float4(f0.x, f1.x, f0.y, f1.y);
            float4 al = make_float4(f0.z, f1.z, f0.w, f1.w);
            #pragma unroll
            for (int n = 0; n < 16; n++){
                float4 bb = BV[n*256 + S*32 + lane];
                uint32_t b0h = __float_as_uint(bb.x), b1h = __float_as_uint(bb.y);
                uint32_t b0l = __float_as_uint(bb.z), b1l = __float_as_uint(bb.w);
                mma8(acc[n], ah, b0h, b1h);
                mma8(acc[n], ah, b0l, b1l);
                mma8(acc[n], al, b0h, b1h);
            }
        }

        // epilogue: exp + row/col sums (logits already scaled by 10 via k-frags)
        float* colPart = sm;
        float rlo = 0.f, rhi = 0.f;
        #pragma unroll
        for (int n = 0; n < 16; n++){
            float e0 = fexp4(acc[n][0]);
            float e1 = fexp4(acc[n][1]);
            float e2 = fexp4(acc[n][2]);
            float e3 = fexp4(acc[n][3]);
            rlo += e0 + e1; rhi += e2 + e3;
            float ca = e0 + e2, cbv = e1 + e3;
            #pragma unroll
            for (int o = 4; o < 32; o <<= 1){
                ca  += __shfl_xor_sync(0xffffffffu, ca,  o);
                cbv += __shfl_xor_sync(0xffffffffu, cbv, o);
            }
            if (lane < 4){
                colPart[wid*128 + n*8 + 2*lane]     = ca;
                colPart[wid*128 + n*8 + 2*lane + 1] = cbv;
            }
        }
        rlo += __shfl_xor_sync(0xffffffffu, rlo, 1);
        rlo += __shfl_xor_sync(0xffffffffu, rlo, 2);
        rhi += __shfl_xor_sync(0xffffffffu, rhi, 1);
        rhi += __shfl_xor_sync(0xffffffffu, rhi, 2);
        if ((lane & 3) == 0){
            atomicAdd(&g_rowsum[rb + wid*16 + (lane >> 2)],     rlo);
            atomicAdd(&g_rowsum[rb + wid*16 + 8 + (lane >> 2)], rhi);
        }
        __syncthreads();
        if (tid < 128){
            float s2 = 0.f;
            #pragma unroll
            for (int w2 = 0; w2 < 8; w2++) s2 += colPart[w2*128 + tid];
            atomicAdd(&g_colsum[cb + tid], s2);
        }
    }

    // ---- final combine: last block ----
    __threadfence();
    __syncthreads();
    if (tid == 0){
        unsigned t = atomicAdd(&g_done, 1u);
        lastFlag = (t == (unsigned)G - 1u) ? 1u : 0u;
    }
    __syncthreads();
    if (lastFlag){
        float ms = 0.f;
        for (int blk = quad; blk < 256; blk += 4)
            ms += __ldcg(&g_meanpart[blk*64 + c]);
        __syncthreads();
        sm[tid] = ms;
        __syncthreads();
        if (tid < 64){
            float Mv = sm[tid] + sm[64+tid] + sm[128+tid] + sm[192+tid];
            sm[256 + tid] = Mv*Mv;
        }
        __syncthreads();

        float tv = __ldcg(&g_timepart[tid]);
        float s = 0.f;
        for (int r = tid; r < 2048; r += 256)
            s += __logf(__ldcg(&g_rowsum[r])) + __logf(__ldcg(&g_colsum[r]))
               - 2.f*__ldcg(&g_diag[r]);
        sm[512 + tid] = tv;
        sm[768 + tid] = s;
        __syncthreads();
        for (int st = 128; st > 0; st >>= 1){
            if (tid < st){
                sm[512+tid] += sm[512+tid+st];
                sm[768+tid] += sm[768+tid+st];
            }
            __syncthreads();
        }
        if (tid == 0){
            float nm2 = 0.f;
            #pragma unroll
            for (int i = 0; i < 64; i++) nm2 += sm[256 + i];
            float normM = sqrtf(nm2);
            float l_con = 0.5f * sm[768] / 2048.f;
            float l_sc  = -normM / 2048.f;
            float l_t   =  sm[512] / 2044.f;
            out[0] = l_con + l_sc + l_t;
            out[1] = l_con;
            out[2] = l_sc;
            out[3] = l_t;
            g_done = 0;   // reset for next graph replay
        }
    }
}

// ---------------- launch ----------------
extern "C" void kernel_launch(void* const* d_in, const int* in_sizes, int n_in,
                              void* d_out, int out_size){
    const float* h      = (const float*)d_in[0];
    const float* x_raw  = (const float*)d_in[1];
    const float* W_in   = (const float*)d_in[2];
    const float* b_in   = (const float*)d_in[3];
    const float* dt_emb = (const float*)d_in[4];
    const float* Wm1    = (const float*)d_in[5];
    const float* bm1    = (const float*)d_in[6];
    const float* Wm2    = (const float*)d_in[7];
    const float* bm2    = (const float*)d_in[8];
    const float* Wg     = (const float*)d_in[9];
    const float* a1     = (const float*)d_in[10];
    const float* a2     = (const float*)d_in[11];
    const float* Wf     = (const float*)d_in[12];
    const float* bf     = (const float*)d_in[13];
    float* out = (float*)d_out;

    const int SMA = SMEMA * 4;
    const int SMB = SMEMB * 4;
    cudaFuncSetAttribute(feat_kernel,   cudaFuncAttributeMaxDynamicSharedMemorySize, SMA);
    cudaFuncSetAttribute(logits_kernel, cudaFuncAttributeMaxDynamicSharedMemorySize, SMB);

    feat_kernel<<<256, 256, SMA>>>(h, x_raw, W_in, b_in, dt_emb, Wm1, bm1, Wm2,
                                   bm2, Wg, a1, a2, Wf, bf);
    logits_kernel<<<256, 256, SMB>>>(out);
}

// round 17
// speedup vs baseline: 1.2016x; 1.1474x over previous
#include <cuda_runtime.h>
#include <cuda_bf16.h>
#include <cstdint>
#include <math.h>

// ---- smem float offsets (feature+attn kernel) ----
#define OH2   0       // h halo 14*128 = 1792
#define OX2   1792    // x halo 14*16 = 224
#define OZT2  2016    // zt 14*64 = 896
#define OWHH2 2912    // wh 14*64 = 896
#define OC2   3808    // gemm partials 4*14*64 = 3584
#define OSI   7392    // si 8*32
#define OSJ   7648    // sj 14*32 = 448
#define OSDP  8096    // 4*32
#define OBM   8224    // 32
#define OWM2  8256    // 32
#define OU1   8288    // 14 (pad 16)
#define OU2   8304    // 14 (pad 16)
#define OES   8320    // 64
#define OAT   8384    // 64
#define OCS   8448    // cs 8*128 = 1024
#define OZR   9472    // z 8*64
#define ONRM  9984    // 32
#define ORED  10016   // 8
#define SMEMA 10048   // kernel A floats (~39KB)
// ---- logits kernel layout ----
#define SMEMB 1056    // colPart 8*128 + final-combine scratch (4.2KB)

// ---------------- scratch (device globals) ----------------
// bf16 fragments, per 8-row group: [S(4)][row|col(8)][j(4)] of uint4
//   q: {ahi(k0,k0+1), ahi(k0+8,k0+9), alo(k0,k0+1), alo(k0+8,k0+9)}
//   k: same, pre-scaled x10 (1/TEMP)
__device__ uint4 g_qfrag[256*128];
__device__ uint4 g_kfrag[256*128];
__device__ float g_rowsum[2048];
__device__ float g_colsum[2048];
__device__ float g_diag[2048];
__device__ float g_meanpart[256*64];
__device__ float g_timepart[256];
__device__ float g_znfirst[256*64];
__device__ float g_znlast[256*64];
__device__ unsigned int g_done = 0;

// Fast exp on FMA pipe (cephes exp2f poly); |x| <= ~80.
__device__ __forceinline__ float fexp(float x){
    float y = x * 1.44269504088896341f;
    float n = rintf(y);
    float f = y - n;
    float p = 1.535336188319500e-4f;
    p = fmaf(p, f, 1.339887440266574e-3f);
    p = fmaf(p, f, 9.618437357674640e-3f);
    p = fmaf(p, f, 5.550332471162809e-2f);
    p = fmaf(p, f, 2.402264791363012e-1f);
    p = fmaf(p, f, 6.931472028550421e-1f);
    p = fmaf(p, f, 1.0f);
    int e = (int)n;
    return p * __int_as_float((e + 127) << 23);
}

// Degree-4 exp (rel err ~1e-5).
__device__ __forceinline__ float fexp4(float x){
    float y = x * 1.44269504088896341f;
    float n = rintf(y);
    float f = y - n;
    float p = 9.618129107628477e-3f;
    p = fmaf(p, f, 5.550410866482158e-2f);
    p = fmaf(p, f, 2.402265069591012e-1f);
    p = fmaf(p, f, 6.931471805599453e-1f);
    p = fmaf(p, f, 1.0f);
    int e = (int)n;
    return p * __int_as_float((e + 127) << 23);
}

__device__ __forceinline__ uint32_t bfpack(float a, float b){
    __nv_bfloat162 p;
    p.x = __float2bfloat16(a);
    p.y = __float2bfloat16(b);
    return *reinterpret_cast<uint32_t*>(&p);
}

// bf16 hi/lo split fragment: {hi(x0,x1), hi(x2,x3), lo(x0,x1), lo(x2,x3)}
__device__ __forceinline__ uint4 packfrag(float x0, float x1, float x2, float x3){
    __nv_bfloat16 h0 = __float2bfloat16(x0), h1 = __float2bfloat16(x1);
    __nv_bfloat16 h2 = __float2bfloat16(x2), h3 = __float2bfloat16(x3);
    float l0 = x0 - __bfloat162float(h0), l1 = x1 - __bfloat162float(h1);
    float l2 = x2 - __bfloat162float(h2), l3 = x3 - __bfloat162float(h3);
    uint4 r;
    __nv_bfloat162 p01; p01.x = h0; p01.y = h1;
    __nv_bfloat162 p23; p23.x = h2; p23.y = h3;
    r.x = *reinterpret_cast<uint32_t*>(&p01);
    r.y = *reinterpret_cast<uint32_t*>(&p23);
    r.z = bfpack(l0, l1);
    r.w = bfpack(l2, l3);
    return r;
}

__device__ __forceinline__ void mma16(float* d, uint32_t a0, uint32_t a1,
                                      uint32_t a2, uint32_t a3,
                                      uint32_t b0, uint32_t b1){
    asm volatile(
        "mma.sync.aligned.m16n8k16.row.col.f32.bf16.bf16.f32 "
        "{%0,%1,%2,%3}, {%4,%5,%6,%7}, {%8,%9}, {%0,%1,%2,%3};\n"
        : "+f"(d[0]), "+f"(d[1]), "+f"(d[2]), "+f"(d[3])
        : "r"(a0), "r"(a1), "r"(a2), "r"(a3), "r"(b0), "r"(b1));
}

// ======================= KERNEL A: features + attention ====================
__global__ void __launch_bounds__(256, 3)
feat_kernel(const float* __restrict__ h,      const float* __restrict__ x_raw,
            const float* __restrict__ W_in,   const float* __restrict__ b_in,
            const float* __restrict__ dt_emb, const float* __restrict__ Wm1,
            const float* __restrict__ bm1,    const float* __restrict__ Wm2,
            const float* __restrict__ bm2,    const float* __restrict__ Wg,
            const float* __restrict__ a1,     const float* __restrict__ a2,
            const float* __restrict__ Wf,     const float* __restrict__ bf)
{
    extern __shared__ float sm[];

    const int tid  = threadIdx.x;
    const int gb   = blockIdx.x;       // 0..255
    const int lane = tid & 31;
    const int wid  = tid >> 5;
    const int c    = tid & 63;
    const int quad = tid >> 6;
    const int rp   = tid >> 6;

    const int gbase = gb*8;
    const int lo = gbase & ~511, hi = lo + 511;
    const int i0 = gbase & 511;

    if (tid < 8)       g_rowsum[gbase + tid] = 0.f;
    else if (tid < 16) g_colsum[gbase + tid - 8] = 0.f;

    // stage h (14 halo rows) and x (14), clamped at sequence edges
    for (int idx = tid; idx < 448; idx += 256){
        int hr = idx >> 5, p = idx & 31;
        int gr = gbase - 3 + hr; gr = gr < lo ? lo : (gr > hi ? hi : gr);
        ((float4*)(sm + OH2))[idx] = ((const float4*)h)[gr*32 + p];
    }
    if (tid < 56){
        int hr = tid >> 2, p = tid & 3;
        int gr = gbase - 3 + hr; gr = gr < lo ? lo : (gr > hi ? hi : gr);
        ((float4*)(sm + OX2))[tid] = ((const float4*)x_raw)[gr*4 + p];
    }
    if (tid >= 64 && tid < 192){
        int t = (tid - 64) >> 5, m = tid & 31;
        float s = 0.f;
        #pragma unroll
        for (int e = 0; e < 8; e++)
            s = fmaf(dt_emb[t*8 + e], Wm1[(32 + e)*32 + m], s);
        sm[OSDP + (tid - 64)] = s;
    } else if (tid >= 192 && tid < 224) sm[OBM  + tid - 192] = bm1[tid - 192];
    else if (tid >= 224)                sm[OWM2 + tid - 224] = Wm2[tid - 224];
    const float bm2v = bm2[0];
    __syncthreads();

    // GEMM1 partials: zt_pre = h @ W_in, 14 rows, quad-split K
    {
        float acc[14];
        #pragma unroll
        for (int r = 0; r < 14; r++) acc[r] = 0.f;
        const float4* H4 = (const float4*)(sm + OH2);
        #pragma unroll
        for (int kk = 0; kk < 8; kk++){
            int kb = quad*32 + kk*4;
            float w0 = W_in[(kb+0)*64 + c];
            float w1 = W_in[(kb+1)*64 + c];
            float w2 = W_in[(kb+2)*64 + c];
            float w3 = W_in[(kb+3)*64 + c];
            #pragma unroll
            for (int r = 0; r < 14; r++){
                float4 v = H4[r*32 + (kb>>2)];
                acc[r] = fmaf(w0, v.x, fmaf(w1, v.y, fmaf(w2, v.z, fmaf(w3, v.w, acc[r]))));
            }
        }
        #pragma unroll
        for (int r = 0; r < 14; r++) sm[OC2 + quad*896 + r*64 + c] = acc[r];
    }
    // si (center 8) / sj (14): warp t -> halo row t
    for (int t = wid; t < 14; t += 8){
        const float* xp = sm + OX2 + t*16;
        float si = 0.f, sj = 0.f;
        #pragma unroll
        for (int q = 0; q < 16; q++){
            float xv = xp[q];
            si = fmaf(xv, Wm1[q*32 + lane], si);
            sj = fmaf(xv, Wm1[(16+q)*32 + lane], sj);
        }
        sm[OSJ + t*32 + lane] = sj;
        if (t >= 3 && t < 11) sm[OSI + (t-3)*32 + lane] = si;
    }
    __syncthreads();

    // zt combine (14 rows)
    {
        float bi = b_in[c];
        for (int r = rp; r < 14; r += 4){
            float z = bi + sm[OC2 + 0*896 + r*64 + c] + sm[OC2 + 1*896 + r*64 + c]
                         + sm[OC2 + 2*896 + r*64 + c] + sm[OC2 + 3*896 + r*64 + c];
            sm[OZT2 + r*64 + c] = fmaxf(z, 0.f);
        }
    }
    __syncthreads();

    // GEMM2 partials: wh = zt @ Wg, 14 rows, K=64
    {
        float acc[14];
        #pragma unroll
        for (int r = 0; r < 14; r++) acc[r] = 0.f;
        const float4* Z4 = (const float4*)(sm + OZT2);
        #pragma unroll
        for (int kk = 0; kk < 4; kk++){
            int kb = quad*16 + kk*4;
            float w0 = Wg[(kb+0)*64 + c];
            float w1 = Wg[(kb+1)*64 + c];
            float w2 = Wg[(kb+2)*64 + c];
            float w3 = Wg[(kb+3)*64 + c];
            #pragma unroll
            for (int r = 0; r < 14; r++){
                float4 v = Z4[r*16 + (kb>>2)];
                acc[r] = fmaf(w0, v.x, fmaf(w1, v.y, fmaf(w2, v.z, fmaf(w3, v.w, acc[r]))));
            }
        }
        #pragma unroll
        for (int r = 0; r < 14; r++) sm[OC2 + quad*896 + r*64 + c] = acc[r];
    }
    __syncthreads();
    {
        for (int r = rp; r < 14; r += 4){
            float whv = sm[OC2 + 0*896 + r*64 + c] + sm[OC2 + 1*896 + r*64 + c]
                      + sm[OC2 + 2*896 + r*64 + c] + sm[OC2 + 3*896 + r*64 + c];
            sm[OWHH2 + r*64 + c] = whv;
        }
    }
    __syncthreads();

    // u1/u2 for 14 halo rows
    for (int t = wid; t < 14; t += 8){
        const float* whp = sm + OWHH2 + t*64;
        float v1 = whp[lane]*a1[lane] + whp[lane+32]*a1[lane+32];
        float v2 = whp[lane]*a2[lane] + whp[lane+32]*a2[lane+32];
        #pragma unroll
        for (int s = 16; s > 0; s >>= 1){
            v1 += __shfl_down_sync(0xffffffffu, v1, s);
            v2 += __shfl_down_sync(0xffffffffu, v2, s);
        }
        if (lane == 0){
            sm[OU1 + t] = v1;
            sm[OU2 + t] = v2;
        }
    }
    __syncthreads();

    // bias: 56 warp-tasks (center row r, offset o)
    for (int t = wid; t < 56; t += 8){
        int r = t / 7, o = t - r*7;
        int jl = i0 + r - 3 + o;
        int jj = r + o;                    // halo index of j
        int dtv = 3 - o; if (dtv < 0) dtv = 0;
        float v = sm[OSI + r*32 + lane] + sm[OSJ + jj*32 + lane]
                + sm[OSDP + dtv*32 + lane] + sm[OBM + lane];
        float p = v > 0.f ? v * sm[OWM2 + lane] : 0.f;
        #pragma unroll
        for (int s = 16; s > 0; s >>= 1) p += __shfl_down_sync(0xffffffffu, p, s);
        if (lane == 0){
            float e = -1e30f;
            if (jl >= 0 && jl < 512){
                float u = sm[OU1 + r + 3] + sm[OU2 + jj];
                float lr = u > 0.f ? u : 0.2f*u;
                e = lr + p + bm2v - 0.2f*(float)dtv;
            }
            sm[OES + r*8 + o] = e;
        }
    }
    __syncthreads();
    if (tid < 8){
        float mx = -1e30f;
        #pragma unroll
        for (int o = 0; o < 7; o++) mx = fmaxf(mx, sm[OES + tid*8 + o]);
        float sum = 0.f, ex[7];
        #pragma unroll
        for (int o = 0; o < 7; o++){
            float e = sm[OES + tid*8 + o];
            ex[o] = e > -1e29f ? fexp(e - mx) : 0.f;
            sum += ex[o];
        }
        float inv = 1.f / sum;
        #pragma unroll
        for (int o = 0; o < 7; o++) sm[OAT + tid*8 + o] = ex[o]*inv;
    }
    __syncthreads();

    // zg = elu(attn @ wh); cs = [zt | zg]  (center rows)
    {
        #pragma unroll
        for (int s = 0; s < 2; s++){
            int rr = rp + s*4;
            float acc = 0.f;
            #pragma unroll
            for (int o = 0; o < 7; o++)
                acc = fmaf(sm[OAT + rr*8 + o], sm[OWHH2 + (rr+o)*64 + c], acc);
            float zg = acc > 0.f ? acc : fexp(acc) - 1.f;
            sm[OCS + rr*128 + 64 + c] = zg;
            sm[OCS + rr*128 + c]      = sm[OZT2 + (rr+3)*64 + c];
        }
    }
    __syncthreads();

    // GEMM3 partials: z = cs @ Wf, 8 center rows, K=128
    {
        float acc[8] = {0,0,0,0,0,0,0,0};
        const float4* C4 = (const float4*)(sm + OCS);
        #pragma unroll
        for (int kk = 0; kk < 8; kk++){
            int kb = quad*32 + kk*4;
            float w0 = Wf[(kb+0)*64 + c];
            float w1 = Wf[(kb+1)*64 + c];
            float w2 = Wf[(kb+2)*64 + c];
            float w3 = Wf[(kb+3)*64 + c];
            #pragma unroll
            for (int r = 0; r < 8; r++){
                float4 v = C4[r*32 + (kb>>2)];
                acc[r] = fmaf(w0, v.x, fmaf(w1, v.y, fmaf(w2, v.z, fmaf(w3, v.w, acc[r]))));
            }
        }
        #pragma unroll
        for (int r = 0; r < 8; r++) sm[OC2 + quad*512 + r*64 + c] = acc[r];
    }
    __syncthreads();
    {
        float bfc = bf[c];
        #pragma unroll
        for (int s = 0; s < 2; s++){
            int rr = rp + s*4;
            float z = bfc + sm[OC2 + 0*512 + rr*64 + c] + sm[OC2 + 1*512 + rr*64 + c]
                          + sm[OC2 + 2*512 + rr*64 + c] + sm[OC2 + 3*512 + rr*64 + c];
            sm[OZR + rr*64 + c] = fmaxf(z, 0.f);
        }
    }
    __syncthreads();

    // norms: 32 warp-tasks (8 rows x {z, zt, zg, zt.zg})
    for (int t = wid; t < 32; t += 8){
        int r = t >> 2, which = t & 3;
        float v;
        if (which == 0){
            float x1 = sm[OZR + r*64 + lane], x2 = sm[OZR + r*64 + lane + 32];
            v = x1*x1 + x2*x2;
        } else if (which == 1){
            float x1 = sm[OZT2 + (r+3)*64 + lane], x2 = sm[OZT2 + (r+3)*64 + lane + 32];
            v = x1*x1 + x2*x2;
        } else if (which == 2){
            float x1 = sm[OCS + r*128 + 64 + lane], x2 = sm[OCS + r*128 + 96 + lane];
            v = x1*x1 + x2*x2;
        } else {
            v = sm[OZT2 + (r+3)*64 + lane]      * sm[OCS + r*128 + 64 + lane]
              + sm[OZT2 + (r+3)*64 + lane + 32] * sm[OCS + r*128 + 96 + lane];
        }
        #pragma unroll
        for (int s = 16; s > 0; s >>= 1) v += __shfl_down_sync(0xffffffffu, v, s);
        if (lane == 0) sm[ONRM + r*4 + which] = v;
    }
    __syncthreads();

    // diag
    if (tid < 8){
        float invzt = 1.f / fmaxf(sqrtf(sm[ONRM + tid*4 + 1]), 1e-8f);
        float invzg = 1.f / fmaxf(sqrtf(sm[ONRM + tid*4 + 2]), 1e-8f);
        g_diag[gbase + tid] = 10.f * sm[ONRM + tid*4 + 3] * invzt * invzg;
    }
    // bf16 hi/lo fragments: q (tid<128), k pre-scaled x10 (tid>=128)
    // entry e: S = e>>5 (0..3), row = (e>>2)&7, j = e&3; k0 = S*16 + 2j
    {
        int e = tid & 127;
        int S = e >> 5, row = (e >> 2) & 7, j = e & 3;
        int k0 = S*16 + 2*j;
        if (tid < 128){
            float invzt = 1.f / fmaxf(sqrtf(sm[ONRM + row*4 + 1]), 1e-8f);
            const float* zp = sm + OZT2 + (row+3)*64;
            g_qfrag[gb*128 + e] = packfrag(zp[k0]*invzt,   zp[k0+1]*invzt,
                                           zp[k0+8]*invzt, zp[k0+9]*invzt);
        } else {
            float scl = 10.f / fmaxf(sqrtf(sm[ONRM + row*4 + 2]), 1e-8f);
            const float* zp = sm + OCS + row*128 + 64;
            g_kfrag[gb*128 + e] = packfrag(zp[k0]*scl,   zp[k0+1]*scl,
                                           zp[k0+8]*scl, zp[k0+9]*scl);
        }
    }
    if (tid < 64){
        float ms = 0.f;
        float zn0 = 0.f, zn7 = 0.f;
        #pragma unroll
        for (int r = 0; r < 8; r++){
            float invz = 1.f / fmaxf(sqrtf(sm[ONRM + r*4]), 1e-8f);
            float zn = sm[OZR + r*64 + tid] * invz;
            ms += zn;
            if (r == 0) zn0 = zn;
            if (r == 7) zn7 = zn;
        }
        g_meanpart[gb*64 + tid] = ms;
        g_znfirst[gb*64 + tid]  = zn0;
        g_znlast[gb*64 + tid]   = zn7;
    }
    if (wid < 7){
        int r = wid;
        float iz1 = 1.f / fmaxf(sqrtf(sm[ONRM + r*4]), 1e-8f);
        float iz2 = 1.f / fmaxf(sqrtf(sm[ONRM + (r+1)*4]), 1e-8f);
        float d = sm[OZR + r*64 + lane]      * sm[OZR + (r+1)*64 + lane]
                + sm[OZR + r*64 + lane + 32] * sm[OZR + (r+1)*64 + lane + 32];
        #pragma unroll
        for (int s = 16; s > 0; s >>= 1) d += __shfl_down_sync(0xffffffffu, d, s);
        if (lane == 0){
            float dd = 1.f - d*iz1*iz2;
            sm[ORED + r] = dd*dd;
        }
    }
    __syncthreads();
    if (tid == 0){
        float ts = 0.f;
        #pragma unroll
        for (int r = 0; r < 7; r++) ts += sm[ORED + r];
        g_timepart[gb] = ts;
    }
}

// ================ KERNEL B: cross pairs + tensor logits + final ============
__global__ void __launch_bounds__(256, 2)
logits_kernel(float* __restrict__ out)
{
    extern __shared__ float sm[];
    __shared__ unsigned int lastFlag;

    const int tid  = threadIdx.x;
    const int bid  = blockIdx.x;
    const int G    = gridDim.x;
    const int lane = tid & 31;
    const int wid  = tid >> 5;
    const int c    = tid & 63;
    const int quad = tid >> 6;

    // cross time-pair for group bid
    {
        int gb = bid;
        if ((gb & 63) != 63 && wid == 0){
            float d = g_znlast[gb*64 + lane]      * g_znfirst[(gb+1)*64 + lane]
                    + g_znlast[gb*64 + lane + 32] * g_znfirst[(gb+1)*64 + lane + 32];
            #pragma unroll
            for (int s = 16; s > 0; s >>= 1) d += __shfl_down_sync(0xffffffffu, d, s);
            if (lane == 0){
                float dd = 1.f - d;
                g_timepart[gb] += dd*dd;
            }
        }
    }

    // logits tile: 128x128; warp = 16 rows x 128 cols; bf16x3 m16n8k16
    {
        const int rb = (bid & 15) << 7, cb = (bid >> 4) << 7;

        float acc[16][4];
        #pragma unroll
        for (int n = 0; n < 16; n++){
            acc[n][0] = 0.f; acc[n][1] = 0.f; acc[n][2] = 0.f; acc[n][3] = 0.f;
        }

        // A fragments: groups (rb/8 + wid*2) rows g, and +1 rows g+8
        const uint4* qfA = &g_qfrag[((rb >> 3) + wid*2)*128];
        const uint4* qfB = qfA + 128;
        const uint4* BV  = &g_kfrag[(cb >> 3)*128];

        #pragma unroll
        for (int S = 0; S < 4; S++){
            uint4 fa = qfA[S*32 + lane];
            uint4 fb = qfB[S*32 + lane];
            #pragma unroll
            for (int n = 0; n < 16; n++){
                uint4 bb = BV[n*128 + S*32 + lane];
                mma16(acc[n], fa.x, fb.x, fa.y, fb.y, bb.x, bb.y);  // hi*hi
                mma16(acc[n], fa.x, fb.x, fa.y, fb.y, bb.z, bb.w);  // hi*lo
                mma16(acc[n], fa.z, fb.z, fa.w, fb.w, bb.x, bb.y);  // lo*hi
            }
        }

        // epilogue: exp + row/col sums (logits pre-scaled x10 via k-frags)
        float* colPart = sm;
        float rlo = 0.f, rhi = 0.f;
        #pragma unroll
        for (int n = 0; n < 16; n++){
            float e0 = fexp4(acc[n][0]);
            float e1 = fexp4(acc[n][1]);
            float e2 = fexp4(acc[n][2]);
            float e3 = fexp4(acc[n][3]);
            rlo += e0 + e1; rhi += e2 + e3;
            float ca = e0 + e2, cbv = e1 + e3;
            #pragma unroll
            for (int o = 4; o < 32; o <<= 1){
                ca  += __shfl_xor_sync(0xffffffffu, ca,  o);
                cbv += __shfl_xor_sync(0xffffffffu, cbv, o);
            }
            if (lane < 4){
                colPart[wid*128 + n*8 + 2*lane]     = ca;
                colPart[wid*128 + n*8 + 2*lane + 1] = cbv;
            }
        }
        rlo += __shfl_xor_sync(0xffffffffu, rlo, 1);
        rlo += __shfl_xor_sync(0xffffffffu, rlo, 2);
        rhi += __shfl_xor_sync(0xffffffffu, rhi, 1);
        rhi += __shfl_xor_sync(0xffffffffu, rhi, 2);
        if ((lane & 3) == 0){
            atomicAdd(&g_rowsum[rb + wid*16 + (lane >> 2)],     rlo);
            atomicAdd(&g_rowsum[rb + wid*16 + 8 + (lane >> 2)], rhi);
        }
        __syncthreads();
        if (tid < 128){
            float s2 = 0.f;
            #pragma unroll
            for (int w2 = 0; w2 < 8; w2++) s2 += colPart[w2*128 + tid];
            atomicAdd(&g_colsum[cb + tid], s2);
        }
    }

    // ---- final combine: last block ----
    __threadfence();
    __syncthreads();
    if (tid == 0){
        unsigned t = atomicAdd(&g_done, 1u);
        lastFlag = (t == (unsigned)G - 1u) ? 1u : 0u;
    }
    __syncthreads();
    if (lastFlag){
        float ms = 0.f;
        for (int blk = quad; blk < 256; blk += 4)
            ms += __ldcg(&g_meanpart[blk*64 + c]);
        __syncthreads();
        sm[tid] = ms;
        __syncthreads();
        if (tid < 64){
            float Mv = sm[tid] + sm[64+tid] + sm[128+tid] + sm[192+tid];
            sm[256 + tid] = Mv*Mv;
        }
        __syncthreads();

        float tv = __ldcg(&g_timepart[tid]);
        float s = 0.f;
        for (int r = tid; r < 2048; r += 256)
            s += __logf(__ldcg(&g_rowsum[r])) + __logf(__ldcg(&g_colsum[r]))
               - 2.f*__ldcg(&g_diag[r]);
        sm[512 + tid] = tv;
        sm[768 + tid] = s;
        __syncthreads();
        for (int st = 128; st > 0; st >>= 1){
            if (tid < st){
                sm[512+tid] += sm[512+tid+st];
                sm[768+tid] += sm[768+tid+st];
            }
            __syncthreads();
        }
        if (tid == 0){
            float nm2 = 0.f;
            #pragma unroll
            for (int i = 0; i < 64; i++) nm2 += sm[256 + i];
            float normM = sqrtf(nm2);
            float l_con = 0.5f * sm[768] / 2048.f;
            float l_sc  = -normM / 2048.f;
            float l_t   =  sm[512] / 2044.f;
            out[0] = l_con + l_sc + l_t;
            out[1] = l_con;
            out[2] = l_sc;
            out[3] = l_t;
            g_done = 0;   // reset for next graph replay
        }
    }
}

// ---------------- launch ----------------
extern "C" void kernel_launch(void* const* d_in, const int* in_sizes, int n_in,
                              void* d_out, int out_size){
    const float* h      = (const float*)d_in[0];
    const float* x_raw  = (const float*)d_in[1];
    const float* W_in   = (const float*)d_in[2];
    const float* b_in   = (const float*)d_in[3];
    const float* dt_emb = (const float*)d_in[4];
    const float* Wm1    = (const float*)d_in[5];
    const float* bm1    = (const float*)d_in[6];
    const float* Wm2    = (const float*)d_in[7];
    const float* bm2    = (const float*)d_in[8];
    const float* Wg     = (const float*)d_in[9];
    const float* a1     = (const float*)d_in[10];
    const float* a2     = (const float*)d_in[11];
    const float* Wf     = (const float*)d_in[12];
    const float* bf     = (const float*)d_in[13];
    float* out = (float*)d_out;

    const int SMA = SMEMA * 4;
    const int SMB = SMEMB * 4;
    cudaFuncSetAttribute(feat_kernel,   cudaFuncAttributeMaxDynamicSharedMemorySize, SMA);
    cudaFuncSetAttribute(logits_kernel, cudaFuncAttributeMaxDynamicSharedMemorySize, SMB);

    feat_kernel<<<256, 256, SMA>>>(h, x_raw, W_in, b_in, dt_emb, Wm1, bm1, Wm2,
                                   bm2, Wg, a1, a2, Wf, bf);
    logits_kernel<<<256, 256, SMB>>>(out);
}